// round 5
// baseline (speedup 1.0000x reference)
#include <cuda_runtime.h>
#include <cuda_bf16.h>
#include <cstdint>
#include <math.h>

// Problem constants
#define BB 16
#define SS 2048
#define DD 512
#define MTOT (BB*SS)          // 32768
#define KEXT 1536             // 3 * 512 (split-bf16 extended K)

// ---------------- device scratch (no allocations allowed) ----------------
// x buffers: 0 = conv-out fwd, 1 = conv-out bwd, 2 = hw1-out fwd, 3 = hw1-out bwd
__device__ float          g_xf[4][(size_t)MTOT * DD];
__device__ __nv_bfloat16  g_xh[4][(size_t)MTOT * DD];
__device__ __nv_bfloat16  g_xl[4][(size_t)MTOT * DD];
// packed transposed split weights: [8][N=1024][K'=1536] bf16
// index = layer*4 + dir*2 + hw ; rows n, cols k' : [0,512)=hi, [512,1024)=lo, [1024,1536)=hi
__device__ __nv_bfloat16  g_wt[8][(size_t)1024 * KEXT];

// ---------------- small helpers ----------------
__device__ __forceinline__ uint32_t smem_u32(const void* p) {
    return (uint32_t)__cvta_generic_to_shared(p);
}
__device__ __forceinline__ void cp16(void* s, const void* g) {
    asm volatile("cp.async.cg.shared.global [%0], [%1], 16;\n"
                 :: "r"(smem_u32(s)), "l"(g) : "memory");
}
__device__ __forceinline__ void cp_commit() {
    asm volatile("cp.async.commit_group;\n" ::: "memory");
}
__device__ __forceinline__ void cp_wait0() {
    asm volatile("cp.async.wait_group 0;\n" ::: "memory");
}
__device__ __forceinline__ void ldsm4(uint32_t& r0, uint32_t& r1, uint32_t& r2, uint32_t& r3,
                                      uint32_t addr) {
    asm volatile("ldmatrix.sync.aligned.m8n8.x4.shared.b16 {%0,%1,%2,%3}, [%4];\n"
                 : "=r"(r0), "=r"(r1), "=r"(r2), "=r"(r3) : "r"(addr));
}
__device__ __forceinline__ void mma16816(float* c, const uint32_t* a, uint32_t b0, uint32_t b1) {
    asm volatile(
        "mma.sync.aligned.m16n8k16.row.col.f32.bf16.bf16.f32 "
        "{%0,%1,%2,%3},{%4,%5,%6,%7},{%8,%9},{%0,%1,%2,%3};\n"
        : "+f"(c[0]), "+f"(c[1]), "+f"(c[2]), "+f"(c[3])
        : "r"(a[0]), "r"(a[1]), "r"(a[2]), "r"(a[3]), "r"(b0), "r"(b1));
}
__device__ __forceinline__ void split_bf16(float v, __nv_bfloat16& h, __nv_bfloat16& l) {
    h = __float2bfloat16(v);
    l = __float2bfloat16(v - __bfloat162float(h));
}

// ---------------- weight prep: transpose + hi/lo split + K-extension ----------------
// grid (16, 32, 8), block (32, 8)
__global__ void prep_w_kernel(const float* __restrict__ fw_W, const float* __restrict__ bw_W) {
    __shared__ float tile[32][33];
    int wI = blockIdx.z;
    int l  = wI >> 2, dir = (wI >> 1) & 1, hw = wI & 1;
    const float* src = (dir ? bw_W : fw_W) + ((size_t)(l * 2 + hw)) * DD * 1024;
    int kb = blockIdx.x * 32, nb = blockIdx.y * 32;
    int tx = threadIdx.x, ty = threadIdx.y;
#pragma unroll
    for (int i = 0; i < 4; i++) {
        int k = kb + ty + i * 8;
        tile[ty + i * 8][tx] = src[(size_t)k * 1024 + nb + tx];
    }
    __syncthreads();
    __nv_bfloat16* dst = g_wt[wI];
#pragma unroll
    for (int i = 0; i < 4; i++) {
        int n = nb + ty + i * 8;
        int k = kb + tx;
        float v = tile[tx][ty + i * 8];
        __nv_bfloat16 h, lo;
        split_bf16(v, h, lo);
        size_t base = (size_t)n * KEXT;
        dst[base + k]        = h;
        dst[base + 512 + k]  = lo;
        dst[base + 1024 + k] = h;
    }
}

// ---------------- band conv (17 taps, scalar weights) + hi/lo emit ----------------
// grid (512, 16), block (128, 4).  x is float4-typed; xRow4 = float4s per (b,s) row; xOff4 = offset.
__global__ void band_conv_kernel(const float4* __restrict__ x, int xRow4, int xOff4,
                                 const float* __restrict__ w, int causal, int outIdx) {
    int c4 = threadIdx.x;                                  // 0..127  (4 channels each)
    int t  = blockIdx.x * blockDim.y + threadIdx.y;        // 0..2047
    int b  = blockIdx.y;
    float wr[17];
#pragma unroll
    for (int i = 0; i < 17; i++) wr[i] = w[i];

    float4 acc = make_float4(0.f, 0.f, 0.f, 0.f);
#pragma unroll
    for (int d = 0; d <= 16; d++) {
        int ts = causal ? (t - d) : (t + d);
        float wd = causal ? wr[16 - d] : wr[d];
        if (ts >= 0 && ts < SS) {
            float4 v = x[(size_t)(b * SS + ts) * xRow4 + xOff4 + c4];
            acc.x += wd * v.x; acc.y += wd * v.y; acc.z += wd * v.z; acc.w += wd * v.w;
        }
    }
    size_t o = ((size_t)(b * SS + t)) * DD + c4 * 4;
    *reinterpret_cast<float4*>(&g_xf[outIdx][o]) = acc;

    __nv_bfloat16 h0, l0, h1, l1, h2, l2, h3, l3;
    split_bf16(acc.x, h0, l0); split_bf16(acc.y, h1, l1);
    split_bf16(acc.z, h2, l2); split_bf16(acc.w, h3, l3);
    __nv_bfloat162* ph = reinterpret_cast<__nv_bfloat162*>(&g_xh[outIdx][o]);
    __nv_bfloat162* pl = reinterpret_cast<__nv_bfloat162*>(&g_xl[outIdx][o]);
    ph[0] = __nv_bfloat162(h0, h1); ph[1] = __nv_bfloat162(h2, h3);
    pl[0] = __nv_bfloat162(l0, l1); pl[1] = __nv_bfloat162(l2, l3);
}

// ---------------- fused split-bf16 GEMM + highway epilogue ----------------
// CTA: 128 rows x (64 nl cols + 64 gate cols).  grid (8, 256), block 256.
// K' = 1536 in 48 chunks of 32, double-buffered cp.async.
// smem rows padded to 40 bf16 (80B) -> ldmatrix conflict-free.
__global__ __launch_bounds__(256) void gemm_hw_kernel(
    int xIdx, int wIdx, const float* __restrict__ bias,
    float* __restrict__ outF, int outStride, int outOff, int outHL) {
    __shared__ __nv_bfloat16 sA[2][128][40];
    __shared__ __nv_bfloat16 sB[2][128][40];

    const __nv_bfloat16* Xh = g_xh[xIdx];
    const __nv_bfloat16* Xl = g_xl[xIdx];
    const float*         Xf = g_xf[xIdx];
    const __nv_bfloat16* Wt = g_wt[wIdx];
    float* of = outF ? outF : g_xf[outHL];

    int tid  = threadIdx.x;
    int warp = tid >> 5, lane = tid & 31;
    int m0 = blockIdx.y * 128;
    int n0 = blockIdx.x * 64;

    float acc[16][4];
#pragma unroll
    for (int t = 0; t < 16; t++)
#pragma unroll
        for (int j = 0; j < 4; j++) acc[t][j] = 0.f;

    const int lrow  = tid >> 2;        // 0..63
    const int lcol8 = (tid & 3) * 8;   // 0,8,16,24
    const size_t aRow0 = (size_t)(m0 + lrow) * DD;
    const size_t aRow1 = (size_t)(m0 + lrow + 64) * DD;
    const size_t bRow0 = (size_t)(n0 + lrow) * KEXT;          // nl columns
    const size_t bRow1 = (size_t)(512 + n0 + lrow) * KEXT;    // gate columns

    // prologue: chunk 0 (phase 0 -> Xh, kA = lcol8)
    cp16(&sA[0][lrow][lcol8],      Xh + aRow0 + lcol8);
    cp16(&sA[0][lrow + 64][lcol8], Xh + aRow1 + lcol8);
    cp16(&sB[0][lrow][lcol8],      Wt + bRow0 + lcol8);
    cp16(&sB[0][lrow + 64][lcol8], Wt + bRow1 + lcol8);
    cp_commit();

    for (int c = 0; c < 48; c++) {
        int buf = c & 1;
        cp_wait0();
        __syncthreads();
        if (c + 1 < 48) {
            int nb = buf ^ 1;
            int cn = c + 1;
            const __nv_bfloat16* Xs = (cn < 32) ? Xh : Xl;
            int kA = (cn & 15) * 32 + lcol8;
            int kB = cn * 32 + lcol8;
            cp16(&sA[nb][lrow][lcol8],      Xs + aRow0 + kA);
            cp16(&sA[nb][lrow + 64][lcol8], Xs + aRow1 + kA);
            cp16(&sB[nb][lrow][lcol8],      Wt + bRow0 + kB);
            cp16(&sB[nb][lrow + 64][lcol8], Wt + bRow1 + kB);
            cp_commit();
        }
#pragma unroll
        for (int ks = 0; ks < 2; ks++) {
            const int kk = ks * 16;
            uint32_t a[4];
            {
                int r   = (warp << 4) + (lane & 15);
                int col = kk + ((lane >> 4) << 3);
                ldsm4(a[0], a[1], a[2], a[3], smem_u32(&sA[buf][r][col]));
            }
#pragma unroll
            for (int tp = 0; tp < 8; tp++) {
                int r   = (tp << 4) + ((lane >> 4) << 3) + (lane & 7);
                int col = kk + (((lane >> 3) & 1) << 3);
                uint32_t b0, b1, b2, b3;
                ldsm4(b0, b1, b2, b3, smem_u32(&sB[buf][r][col]));
                mma16816(acc[2 * tp],     a, b0, b1);
                mma16816(acc[2 * tp + 1], a, b2, b3);
            }
        }
    }

    // ---- highway epilogue (in-register: frag t = nl, frag t+8 = gate) ----
    int mr = m0 + (warp << 4) + (lane >> 2);
    int qc = (lane & 3) * 2;
#pragma unroll
    for (int t = 0; t < 8; t++) {
#pragma unroll
        for (int j = 0; j < 2; j++) {
            int d = n0 + t * 8 + qc + j;
            float b_nl = __ldg(&bias[d]);
            float b_g  = __ldg(&bias[512 + d]);
#pragma unroll
            for (int rh = 0; rh < 2; rh++) {
                int row = mr + rh * 8;
                float nl = acc[t][rh * 2 + j] + b_nl;
                float gt = acc[t + 8][rh * 2 + j] + b_g;
                float g  = 1.f / (1.f + __expf(-gt));
                float xv = Xf[(size_t)row * DD + d];
                float y  = g * xv + (1.f - g) * fmaxf(nl, 0.f);
                of[(size_t)row * outStride + outOff + d] = y;
                if (outHL >= 0) {
                    __nv_bfloat16 h, lo;
                    split_bf16(y, h, lo);
                    g_xh[outHL][(size_t)row * DD + d] = h;
                    g_xl[outHL][(size_t)row * DD + d] = lo;
                }
            }
        }
    }
}

// ---------------- launch ----------------
extern "C" void kernel_launch(void* const* d_in, const int* in_sizes, int n_in,
                              void* d_out, int out_size) {
    const float* inputs  = (const float*)d_in[0];
    // d_in[1] = masks (all ones; unused by reference)
    const float* fw_band = (const float*)d_in[2];
    const float* bw_band = (const float*)d_in[3];
    const float* fw_W    = (const float*)d_in[4];
    const float* fw_b    = (const float*)d_in[5];
    const float* bw_W    = (const float*)d_in[6];
    const float* bw_b    = (const float*)d_in[7];
    float* out = (float*)d_out;

    prep_w_kernel<<<dim3(16, 32, 8), dim3(32, 8)>>>(fw_W, bw_W);

    const dim3 cg(SS / 4, BB), cb(128, 4);
    const dim3 gg(8, MTOT / 128), gb(256);
    const size_t OUT_L = (size_t)BB * SS * 1024;

    for (int l = 0; l < 2; l++) {
        const float4* xin;
        int xr4;
        if (l == 0) { xin = (const float4*)inputs; xr4 = DD / 4; }
        else        { xin = (const float4*)out;    xr4 = 1024 / 4; }  // layer-0 output
        int bwdOff4 = (l == 0) ? 0 : (512 / 4);

        band_conv_kernel<<<cg, cb>>>(xin, xr4, 0,       fw_band + l * 17, 1, 0);
        band_conv_kernel<<<cg, cb>>>(xin, xr4, bwdOff4, bw_band + l * 17, 0, 1);

        // highway 1 (writes fp32 + hi/lo into buffers 2/3)
        gemm_hw_kernel<<<gg, gb>>>(0, l * 4 + 0, fw_b + (size_t)(l * 2) * 1024,
                                   nullptr, DD, 0, 2);
        gemm_hw_kernel<<<gg, gb>>>(1, l * 4 + 2, bw_b + (size_t)(l * 2) * 1024,
                                   nullptr, DD, 0, 3);
        // highway 2 (writes straight into d_out slices)
        gemm_hw_kernel<<<gg, gb>>>(2, l * 4 + 1, fw_b + (size_t)(l * 2 + 1) * 1024,
                                   out + l * OUT_L, 1024, 0, -1);
        gemm_hw_kernel<<<gg, gb>>>(3, l * 4 + 3, bw_b + (size_t)(l * 2 + 1) * 1024,
                                   out + l * OUT_L, 1024, 512, -1);
    }
}